// round 4
// baseline (speedup 1.0000x reference)
#include <cuda_runtime.h>
#include <cuda_bf16.h>

// RelativeAttention: B=2,H=8,S=512,D=64
// scores = (Q.K + Q.R[q,k]) / 8, masked(-1e9), softmax, masked(0), out = p @ V
// Masked (q,k) need NEITHER their R row NOR their K dot -> single fused pass
// over the compacted unmasked index list (~50% of R's 1.07GB skipped).
// Small blocks (TQ=4, 128 thr) -> 10 blocks/SM -> 40 warps: latency hiding via
// occupancy * per-warp MLP.
// Outputs concatenated in d_out: out [B,H,S,D] then p_attn [B,H,S,S].

#define Bc 2
#define Hc 8
#define Sc 512
#define Dc 64
#define TQ 4          // query rows per block (one per warp)
#define THREADS 128
#define FULLM 0xffffffffu

__global__ __launch_bounds__(THREADS, 10)  // ~51-reg budget, 10 CTAs/SM
void relattn_kernel(const float* __restrict__ Q, const float* __restrict__ K,
                    const float* __restrict__ V, const float* __restrict__ R,
                    const int* __restrict__ M,
                    float* __restrict__ out, float* __restrict__ p_out)
{
    __shared__ float q_sh[TQ][Dc];                   // 1 KB
    __shared__ float p_sh[TQ][Sc];                   // 8 KB
    __shared__ unsigned short idx_sh[TQ][Sc + 8];    // 4.1 KB

    const int qt   = blockIdx.x;
    const int h    = blockIdx.y;
    const int b    = blockIdx.z;
    const int tid  = threadIdx.x;
    const int w    = tid >> 5;
    const int lane = tid & 31;

    const int q0 = qt * TQ;
    const int qrow = q0 + w;
    const long bh = (long)b * Hc + h;

    const float* Qb   = Q + (bh * Sc + q0) * Dc;
    const float* Kb   = K + bh * Sc * Dc;
    const float* Vb   = V + bh * Sc * Dc;
    const float* Rrow = R + ((bh * Sc + (long)qrow) * (long)Sc) * Dc;
    const int*   Mrow = M + (((long)b * Sc + qrow) * Sc);

    for (int i = tid; i < TQ * Dc; i += THREADS)
        q_sh[i / Dc][i % Dc] = Qb[i];
    __syncthreads();

    // ---- per-warp mask compaction; keep mask bits in registers ----
    unsigned mbits[Sc / 32];
    int cnt = 0;
    #pragma unroll
    for (int i = 0; i < Sc / 32; ++i) {
        const int kk = i * 32 + lane;
        const bool m = (__ldg(Mrow + kk) != 0);
        const unsigned bal = __ballot_sync(FULLM, m);
        mbits[i] = bal;
        const int pos = cnt + __popc(bal & ((1u << lane) - 1u));
        if (m) idx_sh[w][pos] = (unsigned short)kk;
        cnt += __popc(bal);
    }
    __syncwarp();
    if (lane < 8) idx_sh[w][cnt + lane] = (cnt > 0) ? idx_sh[w][0] : (unsigned short)0;
    __syncwarp();

    // ---- fused scores pass: q . (R_k + K_k) for unmasked k only ----
    const int rg = lane >> 3;            // row within group of 4
    const int l8 = lane & 7;             // float4 slot within first half-row
    const float4 qa = ((const float4*)q_sh[w])[l8];
    const float4 qb = ((const float4*)q_sh[w])[l8 + 8];

    const int cnt4 = (cnt + 3) & ~3;
    #pragma unroll 2
    for (int j = 0; j < cnt4; j += 4) {
        const int jj = j + rg;
        const int kk = (int)idx_sh[w][jj];               // pad-safe address
        const float* rrow = Rrow + (long)kk * Dc;
        const float* krow = Kb   + (long)kk * Dc;
        const float4 ra = __ldcs((const float4*)rrow + l8);
        const float4 rb = __ldcs((const float4*)rrow + l8 + 8);
        const float4 ka = __ldg((const float4*)krow + l8);
        const float4 kb = __ldg((const float4*)krow + l8 + 8);
        float s = qa.x * (ra.x + ka.x) + qa.y * (ra.y + ka.y)
                + qa.z * (ra.z + ka.z) + qa.w * (ra.w + ka.w)
                + qb.x * (rb.x + kb.x) + qb.y * (rb.y + kb.y)
                + qb.z * (rb.z + kb.z) + qb.w * (rb.w + kb.w);
        s += __shfl_xor_sync(FULLM, s, 4);
        s += __shfl_xor_sync(FULLM, s, 2);
        s += __shfl_xor_sync(FULLM, s, 1);
        if (l8 == 0 && jj < cnt) p_sh[w][kk] = s;
    }
    __syncwarp();

    // ---- masked softmax (p_sh garbage at masked kk is selected away) ----
    float vals[Sc / 32];
    float mx = -3.0e38f;
    #pragma unroll
    for (int i = 0; i < Sc / 32; ++i) {
        const int kk = lane + 32 * i;
        const bool um = (mbits[i] >> lane) & 1u;
        float s = um ? p_sh[w][kk] * 0.125f : -1e9f;
        vals[i] = s;
        mx = fmaxf(mx, s);
    }
    #pragma unroll
    for (int o = 16; o; o >>= 1) mx = fmaxf(mx, __shfl_xor_sync(FULLM, mx, o));
    float sum = 0.f;
    #pragma unroll
    for (int i = 0; i < Sc / 32; ++i) {
        const float e = __expf(vals[i] - mx);
        vals[i] = e;
        sum += e;
    }
    #pragma unroll
    for (int o = 16; o; o >>= 1) sum += __shfl_xor_sync(FULLM, sum, o);
    const float inv = 1.0f / sum;

    float* prow = p_out + (bh * Sc + (long)qrow) * Sc;
    #pragma unroll
    for (int i = 0; i < Sc / 32; ++i) {
        const int kk = lane + 32 * i;
        const bool um = (mbits[i] >> lane) & 1u;
        const float p = um ? vals[i] * inv : 0.f;
        p_sh[w][kk] = p;
        __stcs(prow + kk, p);
    }
    __syncwarp();

    // ---- AV over compacted indices, 4 accumulators ----
    float2 acc0 = make_float2(0.f, 0.f), acc1 = make_float2(0.f, 0.f);
    const int cnt2 = (cnt + 1) & ~1;
    #pragma unroll 4
    for (int j = 0; j < cnt2; j += 2) {
        const int k0 = (int)idx_sh[w][j];
        const int k1 = (int)idx_sh[w][j + 1];
        const float p0 = p_sh[w][k0];
        const float p1 = (j + 1 < cnt) ? p_sh[w][k1] : 0.f;
        const float2 v0 = __ldg((const float2*)(Vb + (long)k0 * Dc) + lane);
        const float2 v1 = __ldg((const float2*)(Vb + (long)k1 * Dc) + lane);
        acc0.x += p0 * v0.x; acc0.y += p0 * v0.y;
        acc1.x += p1 * v1.x; acc1.y += p1 * v1.y;
    }
    float* orow = out + (bh * Sc + (long)qrow) * Dc;
    ((float2*)orow)[lane] = make_float2(acc0.x + acc1.x, acc0.y + acc1.y);
}

extern "C" void kernel_launch(void* const* d_in, const int* in_sizes, int n_in,
                              void* d_out, int out_size)
{
    const float* Q = (const float*)d_in[0];
    const float* K = (const float*)d_in[1];
    const float* V = (const float*)d_in[2];
    const float* R = (const float*)d_in[3];
    const int*   M = (const int*)d_in[4];

    float* out   = (float*)d_out;                    // [B,H,S,D]
    float* p_out = out + (long)Bc * Hc * Sc * Dc;    // [B,H,S,S] appended

    dim3 grid(Sc / TQ, Hc, Bc);
    relattn_kernel<<<grid, THREADS>>>(Q, K, V, R, M, out, p_out);
}

// round 5
// speedup vs baseline: 1.0453x; 1.0453x over previous
#include <cuda_runtime.h>
#include <cuda_bf16.h>

// RelativeAttention: B=2,H=8,S=512,D=64
// scores = (Q.K + Q.R[q,k]) / 8, masked(-1e9), softmax, masked(0), out = p @ V
// Masked (q,k) need NEITHER their R row NOR their K dot -> single fused pass
// over the compacted unmasked index list (~50% of R's 1.07GB skipped).
// Grid = 1024 CTAs, each runs EXACTLY 2 tiles and all are resident from t=0:
// no wave quantization tail (round-4 lesson: 1.38 waves wasted ~30% of slots).
// Outputs concatenated in d_out: out [B,H,S,D] then p_attn [B,H,S,S].

#define Bc 2
#define Hc 8
#define Sc 512
#define Dc 64
#define TQ 4          // query rows per tile (one per warp)
#define THREADS 128
#define NTILES 2048   // (Sc/TQ) * Hc * Bc
#define GRIDSZ 1024   // each CTA does 2 tiles
#define FULLM 0xffffffffu

__global__ __launch_bounds__(THREADS, 7)   // 72-reg budget, >=7 CTAs/SM resident
void relattn_kernel(const float* __restrict__ Q, const float* __restrict__ K,
                    const float* __restrict__ V, const float* __restrict__ R,
                    const int* __restrict__ M,
                    float* __restrict__ out, float* __restrict__ p_out)
{
    __shared__ float q_sh[TQ][Dc];                   // 1 KB
    __shared__ float p_sh[TQ][Sc];                   // 8 KB
    __shared__ unsigned short idx_sh[TQ][Sc + 16];   // 4.1 KB

    const int tid  = threadIdx.x;
    const int w    = tid >> 5;
    const int lane = tid & 31;

    const int rg = lane >> 3;            // row within group of 4
    const int l8 = lane & 7;             // float4 slot within first half-row

    for (int t = blockIdx.x; t < NTILES; t += GRIDSZ) {
        const int qt = t & (Sc / TQ - 1);
        const int h  = (t >> 7) & (Hc - 1);
        const int b  = t >> 10;

        const int q0 = qt * TQ;
        const int qrow = q0 + w;
        const long bh = (long)b * Hc + h;

        const float* Qb   = Q + (bh * Sc + q0) * Dc;
        const float* Kb   = K + bh * Sc * Dc;
        const float* Vb   = V + bh * Sc * Dc;
        const float* Rrow = R + ((bh * Sc + (long)qrow) * (long)Sc) * Dc;
        const int*   Mrow = M + (((long)b * Sc + qrow) * Sc);

        __syncthreads();                 // protect q_sh reuse across tiles
        for (int i = tid; i < TQ * Dc; i += THREADS)
            q_sh[i / Dc][i % Dc] = Qb[i];
        __syncthreads();

        // ---- per-warp mask compaction; mask bits kept in registers ----
        unsigned mbits[Sc / 32];
        int cnt = 0;
        #pragma unroll
        for (int i = 0; i < Sc / 32; ++i) {
            const int kk = i * 32 + lane;
            const bool m = (__ldg(Mrow + kk) != 0);
            const unsigned bal = __ballot_sync(FULLM, m);
            mbits[i] = bal;
            const int pos = cnt + __popc(bal & ((1u << lane) - 1u));
            if (m) idx_sh[w][pos] = (unsigned short)kk;
            cnt += __popc(bal);
        }
        __syncwarp();
        if (lane < 16) idx_sh[w][cnt + lane] = (cnt > 0) ? idx_sh[w][0] : (unsigned short)0;
        __syncwarp();

        // ---- fused scores: q . (R_k + K_k) over unmasked k only ----
        const float4 qa = ((const float4*)q_sh[w])[l8];
        const float4 qb = ((const float4*)q_sh[w])[l8 + 8];

        const int cnt4 = (cnt + 3) & ~3;
        #pragma unroll 4
        for (int j = 0; j < cnt4; j += 4) {
            const int jj = j + rg;
            const int kk = (int)idx_sh[w][jj];           // pad-safe address
            const float* rrow = Rrow + (long)kk * Dc;
            const float* krow = Kb   + (long)kk * Dc;
            const float4 ra = __ldcs((const float4*)rrow + l8);
            const float4 rb = __ldcs((const float4*)rrow + l8 + 8);
            const float4 ka = __ldg((const float4*)krow + l8);
            const float4 kb = __ldg((const float4*)krow + l8 + 8);
            float s = qa.x * (ra.x + ka.x) + qa.y * (ra.y + ka.y)
                    + qa.z * (ra.z + ka.z) + qa.w * (ra.w + ka.w)
                    + qb.x * (rb.x + kb.x) + qb.y * (rb.y + kb.y)
                    + qb.z * (rb.z + kb.z) + qb.w * (rb.w + kb.w);
            s += __shfl_xor_sync(FULLM, s, 4);
            s += __shfl_xor_sync(FULLM, s, 2);
            s += __shfl_xor_sync(FULLM, s, 1);
            if (l8 == 0 && jj < cnt) p_sh[w][kk] = s;
        }
        __syncwarp();

        // ---- masked softmax (p_sh garbage at masked kk selected away) ----
        float vals[Sc / 32];
        float mx = -3.0e38f;
        #pragma unroll
        for (int i = 0; i < Sc / 32; ++i) {
            const int kk = lane + 32 * i;
            const bool um = (mbits[i] >> lane) & 1u;
            float s = um ? p_sh[w][kk] * 0.125f : -1e9f;
            vals[i] = s;
            mx = fmaxf(mx, s);
        }
        #pragma unroll
        for (int o = 16; o; o >>= 1) mx = fmaxf(mx, __shfl_xor_sync(FULLM, mx, o));
        float sum = 0.f;
        #pragma unroll
        for (int i = 0; i < Sc / 32; ++i) {
            const float e = __expf(vals[i] - mx);
            vals[i] = e;
            sum += e;
        }
        #pragma unroll
        for (int o = 16; o; o >>= 1) sum += __shfl_xor_sync(FULLM, sum, o);
        const float inv = 1.0f / sum;

        float* prow = p_out + (bh * Sc + (long)qrow) * Sc;
        #pragma unroll
        for (int i = 0; i < Sc / 32; ++i) {
            const int kk = lane + 32 * i;
            const bool um = (mbits[i] >> lane) & 1u;
            const float p = um ? vals[i] * inv : 0.f;
            p_sh[w][kk] = p;
            __stcs(prow + kk, p);
        }
        __syncwarp();

        // ---- AV over compacted indices ----
        float2 acc0 = make_float2(0.f, 0.f), acc1 = make_float2(0.f, 0.f);
        const int cnt2 = (cnt + 1) & ~1;
        #pragma unroll 4
        for (int j = 0; j < cnt2; j += 2) {
            const int k0 = (int)idx_sh[w][j];
            const int k1 = (int)idx_sh[w][j + 1];
            const float p0 = p_sh[w][k0];
            const float p1 = (j + 1 < cnt) ? p_sh[w][k1] : 0.f;
            const float2 v0 = __ldg((const float2*)(Vb + (long)k0 * Dc) + lane);
            const float2 v1 = __ldg((const float2*)(Vb + (long)k1 * Dc) + lane);
            acc0.x += p0 * v0.x; acc0.y += p0 * v0.y;
            acc1.x += p1 * v1.x; acc1.y += p1 * v1.y;
        }
        float* orow = out + (bh * Sc + (long)qrow) * Dc;
        ((float2*)orow)[lane] = make_float2(acc0.x + acc1.x, acc0.y + acc1.y);
    }
}

extern "C" void kernel_launch(void* const* d_in, const int* in_sizes, int n_in,
                              void* d_out, int out_size)
{
    const float* Q = (const float*)d_in[0];
    const float* K = (const float*)d_in[1];
    const float* V = (const float*)d_in[2];
    const float* R = (const float*)d_in[3];
    const int*   M = (const int*)d_in[4];

    float* out   = (float*)d_out;                    // [B,H,S,D]
    float* p_out = out + (long)Bc * Hc * Sc * Dc;    // [B,H,S,S] appended

    relattn_kernel<<<GRIDSZ, THREADS>>>(Q, K, V, R, M, out, p_out);
}

// round 6
// speedup vs baseline: 1.0876x; 1.0405x over previous
#include <cuda_runtime.h>
#include <cuda_bf16.h>

// RelativeAttention: B=2,H=8,S=512,D=64
// scores=(Q.K+Q.R[q,k])/8, mask(-1e9), softmax, mask(0), out=p@V
// ~50% of R's 1.07GB skipped via mask compaction. R streamed with a cp.async
// (LDGSTS) double-buffered pipeline: in-flight bytes live in SMEM, not regs,
// so MLP is no longer register-bound (round-5 lesson).
// Outputs concatenated in d_out: out [B,H,S,D] then p_attn [B,H,S,S].

#define Bc 2
#define Hc 8
#define Sc 512
#define Dc 64
#define TQ 4          // query rows per tile (one per warp)
#define THREADS 128
#define NTILES 2048   // (Sc/TQ)*Hc*Bc
#define GRIDSZ 1024   // 2 contiguous tiles per CTA; 7 CTAs/SM -> all resident
#define CHUNK 8       // R rows per pipeline stage per warp
#define FULLM 0xffffffffu

__device__ __forceinline__ unsigned su32(const void* p) {
    return (unsigned)__cvta_generic_to_shared(p);
}
__device__ __forceinline__ void cp_async16(unsigned sa, const void* g) {
    asm volatile("cp.async.cg.shared.global [%0], [%1], 16;" :: "r"(sa), "l"(g));
}
__device__ __forceinline__ void cp_commit() {
    asm volatile("cp.async.commit_group;" ::: "memory");
}
template<int N> __device__ __forceinline__ void cp_wait() {
    asm volatile("cp.async.wait_group %0;" :: "n"(N) : "memory");
}

__global__ __launch_bounds__(THREADS, 7)   // 72-reg budget, 7 CTAs/SM
void relattn_kernel(const float* __restrict__ Q, const float* __restrict__ K,
                    const float* __restrict__ V, const float* __restrict__ R,
                    const int* __restrict__ M,
                    float* __restrict__ out, float* __restrict__ p_out)
{
    __shared__ float q_sh[TQ][Dc];                     // 1 KB
    __shared__ float p_sh[TQ][Sc];                     // 8 KB
    __shared__ unsigned short idx_sh[TQ][Sc + 16];     // 4.1 KB
    __shared__ float r_buf[TQ][2][CHUNK][Dc];          // 16 KB (R pipeline)

    const int tid  = threadIdx.x;
    const int w    = tid >> 5;
    const int lane = tid & 31;
    const int rg   = lane >> 3;          // row-in-group (4 rows per sub-iter)
    const int l8   = lane & 7;           // float4 slot in half-row
    const int prow = lane >> 4;          // prefetch: row pair selector
    const int pcol = (lane & 15) << 2;   // prefetch: float offset (16B granule)

    for (int ti = 0; ti < 2; ++ti) {
        const int t  = blockIdx.x * 2 + ti;      // contiguous -> same (b,h) reuse
        const int qt = t & (Sc / TQ - 1);
        const int h  = (t >> 7) & (Hc - 1);
        const int b  = t >> 10;

        const int q0 = qt * TQ;
        const int qrow = q0 + w;
        const long bh = (long)b * Hc + h;

        const float* Qb   = Q + (bh * Sc + q0) * Dc;
        const float* Kb   = K + bh * Sc * Dc;
        const float* Vb   = V + bh * Sc * Dc;
        const float* Rrow = R + ((bh * Sc + (long)qrow) * (long)Sc) * Dc;
        const int*   Mrow = M + (((long)b * Sc + qrow) * Sc);

        __syncthreads();                 // q_sh reuse across tiles
        for (int i = tid; i < TQ * Dc; i += THREADS)
            q_sh[i / Dc][i % Dc] = Qb[i];
        __syncthreads();

        // ---- per-warp mask compaction; mask bits kept in registers ----
        unsigned mbits[Sc / 32];
        int cnt = 0;
        #pragma unroll
        for (int i = 0; i < Sc / 32; ++i) {
            const int kk = i * 32 + lane;
            const bool m = (__ldg(Mrow + kk) != 0);
            const unsigned bal = __ballot_sync(FULLM, m);
            mbits[i] = bal;
            const int pos = cnt + __popc(bal & ((1u << lane) - 1u));
            if (m) idx_sh[w][pos] = (unsigned short)kk;
            cnt += __popc(bal);
        }
        __syncwarp();
        if (lane < 16) idx_sh[w][cnt + lane] = (cnt > 0) ? idx_sh[w][0] : (unsigned short)0;
        __syncwarp();

        const float4 qa = ((const float4*)q_sh[w])[l8];
        const float4 qb = ((const float4*)q_sh[w])[l8 + 8];

        // ---- scores with cp.async double-buffered R pipeline ----
        const int nch = (cnt + CHUNK - 1) / CHUNK;

        // prologue: prefetch chunk 0
        if (nch > 0) {
            #pragma unroll
            for (int r = 0; r < 4; ++r) {
                const int rowin = r * 2 + prow;
                const int kk = (int)idx_sh[w][rowin];
                cp_async16(su32(&r_buf[w][0][rowin][pcol]), Rrow + (long)kk * Dc + pcol);
            }
            cp_commit();
        }

        for (int c = 0; c < nch; ++c) {
            const int s = c & 1;
            const int base = c * CHUNK;
            if (c + 1 < nch) {
                const int nb = base + CHUNK;
                #pragma unroll
                for (int r = 0; r < 4; ++r) {
                    const int rowin = r * 2 + prow;
                    const int kk = (int)idx_sh[w][nb + rowin];
                    cp_async16(su32(&r_buf[w][s ^ 1][rowin][pcol]),
                               Rrow + (long)kk * Dc + pcol);
                }
                cp_commit();
                cp_wait<1>();            // chunk c landed
            } else {
                cp_wait<0>();            // drain
            }
            __syncwarp();

            #pragma unroll
            for (int half = 0; half < 2; ++half) {
                const int rowin = (half << 2) + rg;
                const int jj = base + rowin;
                const int kk = (int)idx_sh[w][jj];
                const float* krow = Kb + (long)kk * Dc;
                const float4 ka = __ldg((const float4*)krow + l8);
                const float4 kb = __ldg((const float4*)krow + l8 + 8);
                const float4 ra = *(const float4*)&r_buf[w][s][rowin][l8 << 2];
                const float4 rb = *(const float4*)&r_buf[w][s][rowin][(l8 << 2) + 32];
                float sd = qa.x * (ra.x + ka.x) + qa.y * (ra.y + ka.y)
                         + qa.z * (ra.z + ka.z) + qa.w * (ra.w + ka.w)
                         + qb.x * (rb.x + kb.x) + qb.y * (rb.y + kb.y)
                         + qb.z * (rb.z + kb.z) + qb.w * (rb.w + kb.w);
                sd += __shfl_xor_sync(FULLM, sd, 4);
                sd += __shfl_xor_sync(FULLM, sd, 2);
                sd += __shfl_xor_sync(FULLM, sd, 1);
                if (l8 == 0 && jj < cnt) p_sh[w][kk] = sd;
            }
            __syncwarp();                // stage s consumed before re-fill
        }

        // ---- masked softmax ----
        float vals[Sc / 32];
        float mx = -3.0e38f;
        #pragma unroll
        for (int i = 0; i < Sc / 32; ++i) {
            const int kk = lane + 32 * i;
            const bool um = (mbits[i] >> lane) & 1u;
            float sv = um ? p_sh[w][kk] * 0.125f : -1e9f;
            vals[i] = sv;
            mx = fmaxf(mx, sv);
        }
        #pragma unroll
        for (int o = 16; o; o >>= 1) mx = fmaxf(mx, __shfl_xor_sync(FULLM, mx, o));
        float sum = 0.f;
        #pragma unroll
        for (int i = 0; i < Sc / 32; ++i) {
            const float e = __expf(vals[i] - mx);
            vals[i] = e;
            sum += e;
        }
        #pragma unroll
        for (int o = 16; o; o >>= 1) sum += __shfl_xor_sync(FULLM, sum, o);
        const float inv = 1.0f / sum;

        float* prow2 = p_out + (bh * Sc + (long)qrow) * Sc;
        #pragma unroll
        for (int i = 0; i < Sc / 32; ++i) {
            const int kk = lane + 32 * i;
            const bool um = (mbits[i] >> lane) & 1u;
            const float p = um ? vals[i] * inv : 0.f;
            p_sh[w][kk] = p;
            __stcs(prow2 + kk, p);
        }
        __syncwarp();

        // ---- AV over compacted indices ----
        float2 acc0 = make_float2(0.f, 0.f), acc1 = make_float2(0.f, 0.f);
        const int cnt2 = (cnt + 1) & ~1;
        #pragma unroll 4
        for (int j = 0; j < cnt2; j += 2) {
            const int k0 = (int)idx_sh[w][j];
            const int k1 = (int)idx_sh[w][j + 1];
            const float p0 = p_sh[w][k0];
            const float p1 = (j + 1 < cnt) ? p_sh[w][k1] : 0.f;
            const float2 v0 = __ldg((const float2*)(Vb + (long)k0 * Dc) + lane);
            const float2 v1 = __ldg((const float2*)(Vb + (long)k1 * Dc) + lane);
            acc0.x += p0 * v0.x; acc0.y += p0 * v0.y;
            acc1.x += p1 * v1.x; acc1.y += p1 * v1.y;
        }
        float* orow = out + (bh * Sc + (long)qrow) * Dc;
        ((float2*)orow)[lane] = make_float2(acc0.x + acc1.x, acc0.y + acc1.y);
    }
}

extern "C" void kernel_launch(void* const* d_in, const int* in_sizes, int n_in,
                              void* d_out, int out_size)
{
    const float* Q = (const float*)d_in[0];
    const float* K = (const float*)d_in[1];
    const float* V = (const float*)d_in[2];
    const float* R = (const float*)d_in[3];
    const int*   M = (const int*)d_in[4];

    float* out   = (float*)d_out;                    // [B,H,S,D]
    float* p_out = out + (long)Bc * Hc * Sc * Dc;    // [B,H,S,S] appended

    relattn_kernel<<<GRIDSZ, THREADS>>>(Q, K, V, R, M, out, p_out);
}